// round 10
// baseline (speedup 1.0000x reference)
#include <cuda_runtime.h>
#include <cstdint>

#define N_NODE 50000
#define N_EDGE 600000
#define D 128
#define NREL 3
#define SCAN_CHUNK 4096
#define NCHUNK ((N_NODE + SCAN_CHUNK - 1) / SCAN_CHUNK)   // 13

// ---------------- device scratch (static, no allocs) ----------------
__device__ int   g_deg   [NREL][N_NODE];
__device__ int   g_incl  [NREL][N_NODE];
__device__ int   g_offs  [NREL][N_NODE + 1];
__device__ int   g_cursor[NREL][N_NODE];
__device__ int   g_bsum  [NREL][NCHUNK];
__device__ int   g_sorted[NREL][N_EDGE];

// ---------------- phase 1: count degrees (4 edges / thread, int4) --------
__global__ void count_kernel(const int* __restrict__ e0,
                             const int* __restrict__ e1,
                             const int* __restrict__ e2) {
    int i = blockIdx.x * blockDim.x + threadIdx.x;       // quad index
    int nq = N_EDGE / 4;                                  // 150000
    if (i >= NREL * nq) return;
    int r = i / nq;
    int q = i - r * nq;
    const int* ei = (r == 0) ? e0 : (r == 1) ? e1 : e2;
    int4 dst = *(const int4*)&ei[N_EDGE + q * 4];
    atomicAdd(&g_deg[r][dst.x], 1);
    atomicAdd(&g_deg[r][dst.y], 1);
    atomicAdd(&g_deg[r][dst.z], 1);
    atomicAdd(&g_deg[r][dst.w], 1);
}

// ---------------- phase 2a: per-chunk inclusive scan ----------------
__global__ void scan1_kernel() {
    int r = blockIdx.y;
    int base = blockIdx.x * SCAN_CHUNK + threadIdx.x * 4;
    int v[4];
#pragma unroll
    for (int u = 0; u < 4; u++) {
        int idx = base + u;
        v[u] = (idx < N_NODE) ? g_deg[r][idx] : 0;
    }
    int t = v[0] + v[1] + v[2] + v[3];

    __shared__ int ws[32];
    int lane = threadIdx.x & 31;
    int wid  = threadIdx.x >> 5;
    int s = t;
#pragma unroll
    for (int o = 1; o < 32; o <<= 1) {
        int n = __shfl_up_sync(0xffffffffu, s, o);
        if (lane >= o) s += n;
    }
    if (lane == 31) ws[wid] = s;
    __syncthreads();
    if (wid == 0) {
        int x = ws[lane];
#pragma unroll
        for (int o = 1; o < 32; o <<= 1) {
            int n = __shfl_up_sync(0xffffffffu, x, o);
            if (lane >= o) x += n;
        }
        ws[lane] = x;
    }
    __syncthreads();
    int excl = s - t + (wid ? ws[wid - 1] : 0);
    int run = excl;
#pragma unroll
    for (int u = 0; u < 4; u++) {
        run += v[u];
        int idx = base + u;
        if (idx < N_NODE) g_incl[r][idx] = run;
    }
    if (threadIdx.x == 0) g_bsum[r][blockIdx.x] = ws[31];
}

// ---------------- phase 2b: finalize offsets + cursors (inline chunk scan) --
__global__ void scan3_kernel() {
    int r = blockIdx.y;
    int boff = 0;
#pragma unroll
    for (int c = 0; c < NCHUNK; c++)
        if (c < blockIdx.x) boff += g_bsum[r][c];
    int base = blockIdx.x * SCAN_CHUNK + threadIdx.x * 4;
#pragma unroll
    for (int u = 0; u < 4; u++) {
        int idx = base + u;
        if (idx < N_NODE) {
            int incl = g_incl[r][idx] + boff;
            g_offs[r][idx + 1] = incl;
            g_cursor[r][idx]   = incl - g_deg[r][idx];
        }
    }
    if (blockIdx.x == 0 && threadIdx.x == 0) g_offs[r][0] = 0;
}

// ---------------- phase 3: bucket src ids by dst (4 edges / thread) -------
__global__ void bucket_kernel(const int* __restrict__ e0,
                              const int* __restrict__ e1,
                              const int* __restrict__ e2) {
    int i = blockIdx.x * blockDim.x + threadIdx.x;
    int nq = N_EDGE / 4;
    if (i >= NREL * nq) return;
    int r = i / nq;
    int q = i - r * nq;
    const int* ei = (r == 0) ? e0 : (r == 1) ? e1 : e2;
    int4 src = *(const int4*)&ei[q * 4];
    int4 dst = *(const int4*)&ei[N_EDGE + q * 4];
    g_sorted[r][atomicAdd(&g_cursor[r][dst.x], 1)] = src.x;
    g_sorted[r][atomicAdd(&g_cursor[r][dst.y], 1)] = src.y;
    g_sorted[r][atomicAdd(&g_cursor[r][dst.z], 1)] = src.z;
    g_sorted[r][atomicAdd(&g_cursor[r][dst.w], 1)] = src.w;
}

// ---------------- common TF32 GEMM bits ----------------
#define BM 128
#define BN 128
#define BK 8
#define SROW 12                           // Bs/As row stride (floats)
#define SROW_S 132                        // S row stride
#define NB (((N_NODE) + BM - 1) / BM)     // 391 per output
#define S_BYTES (BM * SROW_S * 4)         // 67584

__device__ __forceinline__ float to_tf32(float x) {
    float r;
    asm("cvt.rna.tf32.f32 %0, %1;" : "=f"(r) : "f"(x));
    return r;
}

#define MMA_TF32(ac, a, b) \
    asm volatile("mma.sync.aligned.m16n8k8.row.col.f32.tf32.tf32.f32 " \
                 "{%0,%1,%2,%3}, {%4,%5,%6,%7}, {%8,%9}, {%0,%1,%2,%3};" \
                 : "+f"((ac)[0]), "+f"((ac)[1]), "+f"((ac)[2]), "+f"((ac)[3]) \
                 : "r"((a)[0]), "r"((a)[1]), "r"((a)[2]), "r"((a)[3]), \
                   "r"((b)[0]), "r"((b)[1]))

struct GemmArgs {
    const float* x_user; const float* x_item;
    const float* Wl_rates; const float* bl_rates; const float* Wr_rates;
    const float* Wl_rev;   const float* bl_rev;   const float* Wr_rev;
    const float* Wl_fol;   const float* bl_fol;   const float* Wr_fol;
    float* out;
};

// ---------------- kernel A: x @ Wr^T + bias (edge-independent) ------------
// Runs concurrently with the preprocessing chain (graph fork).
__global__ void __launch_bounds__(256, 2)
gemm_x_kernel(GemmArgs A_) {
    __shared__ __align__(16) float As[BM * SROW];
    __shared__ __align__(16) float Bs[BM * SROW];

    int out_id = (blockIdx.x >= NB) ? 1 : 0;
    int m0 = (blockIdx.x - out_id * NB) * BM;

    const float* X;
    const float* W;
    const float* W2;
    const float* bias0;
    const float* bias1;
    float scale;
    float* outp;
    if (out_id == 0) {
        X = A_.x_user; W = A_.Wr_rev; W2 = A_.Wr_fol;
        bias0 = A_.bl_rev; bias1 = A_.bl_fol; scale = 0.5f;
        outp = A_.out;
    } else {
        X = A_.x_item; W = A_.Wr_rates; W2 = nullptr;
        bias0 = A_.bl_rates; bias1 = nullptr; scale = 1.0f;
        outp = A_.out + (size_t)N_NODE * D;
    }

    int tid  = threadIdx.x;
    int lane = tid & 31;
    int wid  = tid >> 5;
    int warp_m = wid & 3;
    int warp_n = wid >> 2;
    int g   = lane >> 2;
    int tig = lane & 3;
    int lrow = tid >> 1;
    int lk4  = (tid & 1) * 4;

    float acc[2][8][4];
#pragma unroll
    for (int mt = 0; mt < 2; mt++)
#pragma unroll
        for (int nt = 0; nt < 8; nt++)
#pragma unroll
            for (int c = 0; c < 4; c++) acc[mt][nt][c] = 0.f;

    auto LOAD = [&](int t, float4& avo, float4& bvo) {
        int kk = t * BK;
        int gm = m0 + lrow;
        avo = (gm < N_NODE)
            ? *(const float4*)&X[(size_t)gm * D + kk + lk4]
            : make_float4(0.f, 0.f, 0.f, 0.f);
        float4 b = *(const float4*)&W[(size_t)lrow * D + kk + lk4];
        if (W2) {
            float4 w = *(const float4*)&W2[(size_t)lrow * D + kk + lk4];
            b.x += w.x; b.y += w.y; b.z += w.z; b.w += w.w;
        }
        bvo = b;
    };

    float4 av, bv;
    LOAD(0, av, bv);

    for (int t = 0; t < 16; t++) {
        float4 at, bt;
        at.x = to_tf32(av.x); at.y = to_tf32(av.y);
        at.z = to_tf32(av.z); at.w = to_tf32(av.w);
        bt.x = to_tf32(bv.x); bt.y = to_tf32(bv.y);
        bt.z = to_tf32(bv.z); bt.w = to_tf32(bv.w);
        *(float4*)&As[lrow * SROW + lk4] = at;
        *(float4*)&Bs[lrow * SROW + lk4] = bt;
        __syncthreads();

        float4 av2 = make_float4(0.f, 0.f, 0.f, 0.f);
        float4 bv2 = av2;
        if (t + 1 < 16) LOAD(t + 1, av2, bv2);

        uint32_t a_[2][4];
        const float* Ab = &As[(warp_m * 32) * SROW];
#pragma unroll
        for (int mt = 0; mt < 2; mt++) {
            a_[mt][0] = __float_as_uint(Ab[(mt * 16 + g)     * SROW + tig]);
            a_[mt][1] = __float_as_uint(Ab[(mt * 16 + g + 8) * SROW + tig]);
            a_[mt][2] = __float_as_uint(Ab[(mt * 16 + g)     * SROW + tig + 4]);
            a_[mt][3] = __float_as_uint(Ab[(mt * 16 + g + 8) * SROW + tig + 4]);
        }
        uint32_t b_[8][2];
        const float* Bb = &Bs[(warp_n * 64) * SROW];
#pragma unroll
        for (int nt = 0; nt < 8; nt++) {
            b_[nt][0] = __float_as_uint(Bb[(nt * 8 + g) * SROW + tig]);
            b_[nt][1] = __float_as_uint(Bb[(nt * 8 + g) * SROW + tig + 4]);
        }

#pragma unroll
        for (int mt = 0; mt < 2; mt++)
#pragma unroll
            for (int nt = 0; nt < 8; nt++)
                MMA_TF32(acc[mt][nt], a_[mt], b_[nt]);

        __syncthreads();
        av = av2; bv = bv2;
    }

    float bias_lo[8], bias_hi[8];
#pragma unroll
    for (int nt = 0; nt < 8; nt++) {
        int c = warp_n * 64 + nt * 8 + 2 * tig;
        float b0v = bias0[c];
        float b1v = bias0[c + 1];
        if (bias1) { b0v += bias1[c]; b1v += bias1[c + 1]; }
        bias_lo[nt] = b0v;
        bias_hi[nt] = b1v;
    }
#pragma unroll
    for (int mt = 0; mt < 2; mt++) {
        int r0 = m0 + warp_m * 32 + mt * 16 + g;
        int r1 = r0 + 8;
#pragma unroll
        for (int nt = 0; nt < 8; nt++) {
            int c = warp_n * 64 + nt * 8 + 2 * tig;
            if (r0 < N_NODE) {
                float2 o;
                o.x = scale * (acc[mt][nt][0] + bias_lo[nt]);
                o.y = scale * (acc[mt][nt][1] + bias_hi[nt]);
                *(float2*)&outp[(size_t)r0 * D + c] = o;
            }
            if (r1 < N_NODE) {
                float2 o;
                o.x = scale * (acc[mt][nt][2] + bias_lo[nt]);
                o.y = scale * (acc[mt][nt][3] + bias_hi[nt]);
                *(float2*)&outp[(size_t)r1 * D + c] = o;
            }
        }
    }
}

// ---------------- kernel B: fused aggregate + mean@Wl GEMM, out += --------
__global__ void __launch_bounds__(256, 2)
fused_agg_gemm_kernel(GemmArgs A_) {
    extern __shared__ __align__(16) float S[];      // BM x SROW_S
    __shared__ __align__(16) float Bs[BM * SROW];

    int out_id = (blockIdx.x >= NB) ? 1 : 0;
    int m0 = (blockIdx.x - out_id * NB) * BM;

    int tid  = threadIdx.x;
    int lane = tid & 31;
    int wid  = tid >> 5;
    int warp_m = wid & 3;
    int warp_n = wid >> 2;
    int g   = lane >> 2;
    int tig = lane & 3;
    int lrow = tid >> 1;
    int lk4  = (tid & 1) * 4;

    int aggR[2];
    const float* aggX[2];
    const float* aggW[2];
    float scale;
    int nAgg;
    float* outp;
    if (out_id == 0) {
        aggR[0] = 1; aggX[0] = A_.x_item; aggW[0] = A_.Wl_rev;   // rev: gathers items
        aggR[1] = 2; aggX[1] = A_.x_user; aggW[1] = A_.Wl_fol;   // fol: gathers users
        nAgg = 2; scale = 0.5f;
        outp = A_.out;
    } else {
        aggR[0] = 0; aggX[0] = A_.x_user; aggW[0] = A_.Wl_rates; // rates: gathers users
        aggR[1] = 0; aggX[1] = nullptr;   aggW[1] = nullptr;
        nAgg = 1; scale = 1.0f;
        outp = A_.out + (size_t)N_NODE * D;
    }

    float acc[2][8][4];
#pragma unroll
    for (int mt = 0; mt < 2; mt++)
#pragma unroll
        for (int nt = 0; nt < 8; nt++)
#pragma unroll
            for (int c = 0; c < 4; c++) acc[mt][nt][c] = 0.f;

    for (int s = 0; s < nAgg; s++) {
        int r = aggR[s];
        const float* __restrict__ xs = aggX[s];
        // ---- gather segment means into S (warp per node, 16 nodes/warp) ----
        for (int i = 0; i < 16; i++) {
            int node = m0 + i * 8 + wid;
            float4 a0 = make_float4(0.f, 0.f, 0.f, 0.f);
            float4 a1 = a0, a2 = a0, a3 = a0;
            float inv = 0.f;
            if (node < N_NODE) {
                int beg = g_offs[r][node];
                int end = g_offs[r][node + 1];
                for (int e = beg; e < end; e += 32) {
                    int n = end - e;
                    if (n > 32) n = 32;
                    int idx = (lane < n) ? g_sorted[r][e + lane] : 0;
                    int j = 0;
                    for (; j + 4 <= n; j += 4) {
                        int s0 = __shfl_sync(0xffffffffu, idx, j + 0);
                        int s1 = __shfl_sync(0xffffffffu, idx, j + 1);
                        int s2 = __shfl_sync(0xffffffffu, idx, j + 2);
                        int s3 = __shfl_sync(0xffffffffu, idx, j + 3);
                        float4 v0 = __ldg((const float4*)(xs + (size_t)s0 * D) + lane);
                        float4 v1 = __ldg((const float4*)(xs + (size_t)s1 * D) + lane);
                        float4 v2 = __ldg((const float4*)(xs + (size_t)s2 * D) + lane);
                        float4 v3 = __ldg((const float4*)(xs + (size_t)s3 * D) + lane);
                        a0.x += v0.x; a0.y += v0.y; a0.z += v0.z; a0.w += v0.w;
                        a1.x += v1.x; a1.y += v1.y; a1.z += v1.z; a1.w += v1.w;
                        a2.x += v2.x; a2.y += v2.y; a2.z += v2.z; a2.w += v2.w;
                        a3.x += v3.x; a3.y += v3.y; a3.z += v3.z; a3.w += v3.w;
                    }
                    for (; j < n; j++) {
                        int s0 = __shfl_sync(0xffffffffu, idx, j);
                        float4 v0 = __ldg((const float4*)(xs + (size_t)s0 * D) + lane);
                        a0.x += v0.x; a0.y += v0.y; a0.z += v0.z; a0.w += v0.w;
                    }
                }
                int deg = end - beg;
                inv = (deg > 0) ? (1.0f / (float)deg) : 0.0f;
            }
            float4 o;
            o.x = to_tf32((a0.x + a1.x + a2.x + a3.x) * inv);
            o.y = to_tf32((a0.y + a1.y + a2.y + a3.y) * inv);
            o.z = to_tf32((a0.z + a1.z + a2.z + a3.z) * inv);
            o.w = to_tf32((a0.w + a1.w + a2.w + a3.w) * inv);
            *(float4*)&S[(i * 8 + wid) * SROW_S + lane * 4] = o;
        }
        __syncthreads();

        // ---- 16 k-tiles of MMA: A from S, B from W via Bs ----
        const float* W = aggW[s];
        float4 bv = __ldg((const float4*)(W + (size_t)lrow * D) + (lk4 >> 2));

        for (int t = 0; t < 16; t++) {
            float4 bt;
            bt.x = to_tf32(bv.x); bt.y = to_tf32(bv.y);
            bt.z = to_tf32(bv.z); bt.w = to_tf32(bv.w);
            *(float4*)&Bs[lrow * SROW + lk4] = bt;
            __syncthreads();

            float4 bv2 = make_float4(0.f, 0.f, 0.f, 0.f);
            if (t + 1 < 16) {
                int kk = (t + 1) * BK;
                bv2 = __ldg((const float4*)(W + (size_t)lrow * D) + ((kk + lk4) >> 2));
            }

            int kk = t * BK;
            uint32_t a_[2][4];
            const float* Ab = &S[(warp_m * 32) * SROW_S + kk];
#pragma unroll
            for (int mt = 0; mt < 2; mt++) {
                a_[mt][0] = __float_as_uint(Ab[(mt * 16 + g)     * SROW_S + tig]);
                a_[mt][1] = __float_as_uint(Ab[(mt * 16 + g + 8) * SROW_S + tig]);
                a_[mt][2] = __float_as_uint(Ab[(mt * 16 + g)     * SROW_S + tig + 4]);
                a_[mt][3] = __float_as_uint(Ab[(mt * 16 + g + 8) * SROW_S + tig + 4]);
            }
            uint32_t b_[8][2];
            const float* Bb = &Bs[(warp_n * 64) * SROW];
#pragma unroll
            for (int nt = 0; nt < 8; nt++) {
                b_[nt][0] = __float_as_uint(Bb[(nt * 8 + g) * SROW + tig]);
                b_[nt][1] = __float_as_uint(Bb[(nt * 8 + g) * SROW + tig + 4]);
            }

#pragma unroll
            for (int mt = 0; mt < 2; mt++)
#pragma unroll
                for (int nt = 0; nt < 8; nt++)
                    MMA_TF32(acc[mt][nt], a_[mt], b_[nt]);

            __syncthreads();
            bv = bv2;
        }
    }

    // ---- epilogue: accumulate into out (bias already applied by gemm_x) ----
#pragma unroll
    for (int mt = 0; mt < 2; mt++) {
        int r0 = m0 + warp_m * 32 + mt * 16 + g;
        int r1 = r0 + 8;
#pragma unroll
        for (int nt = 0; nt < 8; nt++) {
            int c = warp_n * 64 + nt * 8 + 2 * tig;
            if (r0 < N_NODE) {
                float2 p = *(const float2*)&outp[(size_t)r0 * D + c];
                p.x += scale * acc[mt][nt][0];
                p.y += scale * acc[mt][nt][1];
                *(float2*)&outp[(size_t)r0 * D + c] = p;
            }
            if (r1 < N_NODE) {
                float2 p = *(const float2*)&outp[(size_t)r1 * D + c];
                p.x += scale * acc[mt][nt][2];
                p.y += scale * acc[mt][nt][3];
                *(float2*)&outp[(size_t)r1 * D + c] = p;
            }
        }
    }
}

// ---------------- launcher ----------------
extern "C" void kernel_launch(void* const* d_in, const int* in_sizes, int n_in,
                              void* d_out, int out_size) {
    const float* x_user   = (const float*)d_in[0];
    const float* x_item   = (const float*)d_in[1];
    const int*   ei_rates = (const int*)d_in[2];
    const int*   ei_rev   = (const int*)d_in[3];
    const int*   ei_fol   = (const int*)d_in[4];
    const float* Wl_rates = (const float*)d_in[5];
    const float* bl_rates = (const float*)d_in[6];
    const float* Wr_rates = (const float*)d_in[7];
    const float* Wl_rev   = (const float*)d_in[8];
    const float* bl_rev   = (const float*)d_in[9];
    const float* Wr_rev   = (const float*)d_in[10];
    const float* Wl_fol   = (const float*)d_in[11];
    const float* bl_fol   = (const float*)d_in[12];
    const float* Wr_fol   = (const float*)d_in[13];

    float* outp = (float*)d_out;

    // one-time setup (first call is the eager correctness run, not captured)
    static cudaStream_t s1 = nullptr;
    static cudaEvent_t evFork = nullptr, evPre = nullptr;
    static int init_done = 0;
    if (!init_done) {
        cudaFuncSetAttribute(fused_agg_gemm_kernel,
                             cudaFuncAttributeMaxDynamicSharedMemorySize,
                             S_BYTES);
        cudaStreamCreateWithFlags(&s1, cudaStreamNonBlocking);
        cudaEventCreateWithFlags(&evFork, cudaEventDisableTiming);
        cudaEventCreateWithFlags(&evPre, cudaEventDisableTiming);
        init_done = 1;
    }

    GemmArgs A_{x_user, x_item,
                Wl_rates, bl_rates, Wr_rates,
                Wl_rev, bl_rev, Wr_rev,
                Wl_fol, bl_fol, Wr_fol,
                outp};

    int nq = NREL * (N_EDGE / 4);

    // ---- fork: preprocessing chain on side stream s1 ----
    cudaEventRecord(evFork, 0);
    cudaStreamWaitEvent(s1, evFork, 0);
    void* degp = nullptr;
    cudaGetSymbolAddress(&degp, g_deg);
    cudaMemsetAsync(degp, 0, sizeof(int) * NREL * N_NODE, s1);
    count_kernel<<<(nq + 255) / 256, 256, 0, s1>>>(ei_rates, ei_rev, ei_fol);
    dim3 sg(NCHUNK, NREL);
    scan1_kernel<<<sg, 1024, 0, s1>>>();
    scan3_kernel<<<sg, 1024, 0, s1>>>();
    bucket_kernel<<<(nq + 255) / 256, 256, 0, s1>>>(ei_rates, ei_rev, ei_fol);
    cudaEventRecord(evPre, s1);

    // ---- main stream: edge-independent x@Wr GEMM (overlaps preprocessing) --
    gemm_x_kernel<<<2 * NB, 256>>>(A_);

    // ---- join, then aggregated sources accumulate into out ----
    cudaStreamWaitEvent(0, evPre, 0);
    fused_agg_gemm_kernel<<<2 * NB, 256, S_BYTES>>>(A_);
}

// round 11
// speedup vs baseline: 1.0849x; 1.0849x over previous
#include <cuda_runtime.h>
#include <cstdint>

#define N_NODE 50000
#define N_EDGE 600000
#define D 128
#define NREL 3
#define SCAN_CHUNK 4096
#define NCHUNK ((N_NODE + SCAN_CHUNK - 1) / SCAN_CHUNK)   // 13

// ---------------- device scratch (static, no allocs; zero-initialized) ----
__device__ int   g_deg   [NREL][N_NODE];   // re-zeroed by scan3 each run
__device__ int   g_incl  [NREL][N_NODE];
__device__ int   g_offs  [NREL][N_NODE + 1];
__device__ int   g_cursor[NREL][N_NODE];
__device__ int   g_bsum  [NREL][NCHUNK];
__device__ int   g_sorted[NREL][N_EDGE];

// ---------------- phase 1: count degrees (4 edges / thread, int4) --------
__global__ void count_kernel(const int* __restrict__ e0,
                             const int* __restrict__ e1,
                             const int* __restrict__ e2) {
    int i = blockIdx.x * blockDim.x + threadIdx.x;       // quad index
    int nq = N_EDGE / 4;                                  // 150000
    if (i >= NREL * nq) return;
    int r = i / nq;
    int q = i - r * nq;
    const int* ei = (r == 0) ? e0 : (r == 1) ? e1 : e2;
    int4 dst = *(const int4*)&ei[N_EDGE + q * 4];
    atomicAdd(&g_deg[r][dst.x], 1);
    atomicAdd(&g_deg[r][dst.y], 1);
    atomicAdd(&g_deg[r][dst.z], 1);
    atomicAdd(&g_deg[r][dst.w], 1);
}

// ---------------- phase 2a: per-chunk inclusive scan ----------------
__global__ void scan1_kernel() {
    int r = blockIdx.y;
    int base = blockIdx.x * SCAN_CHUNK + threadIdx.x * 4;
    int v[4];
#pragma unroll
    for (int u = 0; u < 4; u++) {
        int idx = base + u;
        v[u] = (idx < N_NODE) ? g_deg[r][idx] : 0;
    }
    int t = v[0] + v[1] + v[2] + v[3];

    __shared__ int ws[32];
    int lane = threadIdx.x & 31;
    int wid  = threadIdx.x >> 5;
    int s = t;
#pragma unroll
    for (int o = 1; o < 32; o <<= 1) {
        int n = __shfl_up_sync(0xffffffffu, s, o);
        if (lane >= o) s += n;
    }
    if (lane == 31) ws[wid] = s;
    __syncthreads();
    if (wid == 0) {
        int x = ws[lane];
#pragma unroll
        for (int o = 1; o < 32; o <<= 1) {
            int n = __shfl_up_sync(0xffffffffu, x, o);
            if (lane >= o) x += n;
        }
        ws[lane] = x;
    }
    __syncthreads();
    int excl = s - t + (wid ? ws[wid - 1] : 0);
    int run = excl;
#pragma unroll
    for (int u = 0; u < 4; u++) {
        run += v[u];
        int idx = base + u;
        if (idx < N_NODE) g_incl[r][idx] = run;
    }
    if (threadIdx.x == 0) g_bsum[r][blockIdx.x] = ws[31];
}

// ---------------- phase 2b: finalize offsets + cursors; re-zero g_deg -----
__global__ void scan3_kernel() {
    int r = blockIdx.y;
    int boff = 0;
#pragma unroll
    for (int c = 0; c < NCHUNK; c++)
        if (c < blockIdx.x) boff += g_bsum[r][c];
    int base = blockIdx.x * SCAN_CHUNK + threadIdx.x * 4;
#pragma unroll
    for (int u = 0; u < 4; u++) {
        int idx = base + u;
        if (idx < N_NODE) {
            int incl = g_incl[r][idx] + boff;
            g_offs[r][idx + 1] = incl;
            g_cursor[r][idx]   = incl - g_deg[r][idx];
            g_deg[r][idx]      = 0;      // ready for next replay
        }
    }
    if (blockIdx.x == 0 && threadIdx.x == 0) g_offs[r][0] = 0;
}

// ---------------- phase 3: bucket src ids by dst (4 edges / thread) -------
__global__ void bucket_kernel(const int* __restrict__ e0,
                              const int* __restrict__ e1,
                              const int* __restrict__ e2) {
    int i = blockIdx.x * blockDim.x + threadIdx.x;
    int nq = N_EDGE / 4;
    if (i >= NREL * nq) return;
    int r = i / nq;
    int q = i - r * nq;
    const int* ei = (r == 0) ? e0 : (r == 1) ? e1 : e2;
    int4 src = *(const int4*)&ei[q * 4];
    int4 dst = *(const int4*)&ei[N_EDGE + q * 4];
    g_sorted[r][atomicAdd(&g_cursor[r][dst.x], 1)] = src.x;
    g_sorted[r][atomicAdd(&g_cursor[r][dst.y], 1)] = src.y;
    g_sorted[r][atomicAdd(&g_cursor[r][dst.z], 1)] = src.z;
    g_sorted[r][atomicAdd(&g_cursor[r][dst.w], 1)] = src.w;
}

// ---------------- phase 4: FUSED aggregate + TF32 GEMM (R9 structure) -----
#define BM 128
#define BN 128
#define BK 8
#define SROW 12                           // Bs row stride (floats)
#define SROW_S 132                        // S row stride
#define NB (((N_NODE) + BM - 1) / BM)     // 391 per output
#define S_BYTES (BM * SROW_S * 4)         // 67584

__device__ __forceinline__ float to_tf32(float x) {
    float r;
    asm("cvt.rna.tf32.f32 %0, %1;" : "=f"(r) : "f"(x));
    return r;
}

#define MMA_TF32(ac, a, b) \
    asm volatile("mma.sync.aligned.m16n8k8.row.col.f32.tf32.tf32.f32 " \
                 "{%0,%1,%2,%3}, {%4,%5,%6,%7}, {%8,%9}, {%0,%1,%2,%3};" \
                 : "+f"((ac)[0]), "+f"((ac)[1]), "+f"((ac)[2]), "+f"((ac)[3]) \
                 : "r"((a)[0]), "r"((a)[1]), "r"((a)[2]), "r"((a)[3]), \
                   "r"((b)[0]), "r"((b)[1]))

struct GemmArgs {
    const float* x_user; const float* x_item;
    const float* Wl_rates; const float* bl_rates; const float* Wr_rates;
    const float* Wl_rev;   const float* bl_rev;   const float* Wr_rev;
    const float* Wl_fol;   const float* bl_fol;   const float* Wr_fol;
    float* out;
};

__global__ void __launch_bounds__(256, 2)
fused_agg_gemm_kernel(GemmArgs A_) {
    extern __shared__ __align__(16) float S[];      // BM x SROW_S
    __shared__ __align__(16) float Bs[BM * SROW];

    int out_id = (blockIdx.x >= NB) ? 1 : 0;
    int m0 = (blockIdx.x - out_id * NB) * BM;

    int tid  = threadIdx.x;
    int lane = tid & 31;
    int wid  = tid >> 5;
    int warp_m = wid & 3;
    int warp_n = wid >> 2;
    int g   = lane >> 2;
    int tig = lane & 3;
    int lrow = tid >> 1;
    int lk4  = (tid & 1) * 4;

    // source plan
    int aggR[2];
    const float* aggX[2];
    const float* aggW[2];
    const float* xsrc;
    const float* wx;
    const float* wxb;
    const float* bias0;
    const float* bias1;
    float scale;
    int nAgg;
    float* outp;
    if (out_id == 0) {
        aggR[0] = 1; aggX[0] = A_.x_item; aggW[0] = A_.Wl_rev;   // rev: gathers items
        aggR[1] = 2; aggX[1] = A_.x_user; aggW[1] = A_.Wl_fol;   // fol: gathers users
        nAgg = 2;
        xsrc = A_.x_user; wx = A_.Wr_rev; wxb = A_.Wr_fol;
        bias0 = A_.bl_rev; bias1 = A_.bl_fol; scale = 0.5f;
        outp = A_.out;
    } else {
        aggR[0] = 0; aggX[0] = A_.x_user; aggW[0] = A_.Wl_rates; // rates: gathers users
        aggR[1] = 0; aggX[1] = nullptr;   aggW[1] = nullptr;
        nAgg = 1;
        xsrc = A_.x_item; wx = A_.Wr_rates; wxb = nullptr;
        bias0 = A_.bl_rates; bias1 = nullptr; scale = 1.0f;
        outp = A_.out + (size_t)N_NODE * D;
    }

    float acc[2][8][4];
#pragma unroll
    for (int mt = 0; mt < 2; mt++)
#pragma unroll
        for (int nt = 0; nt < 8; nt++)
#pragma unroll
            for (int c = 0; c < 4; c++) acc[mt][nt][c] = 0.f;

    for (int s = 0; s <= nAgg; s++) {
        bool isAgg = (s < nAgg);
        const float* W  = isAgg ? aggW[s] : wx;
        const float* W2 = (!isAgg) ? wxb : nullptr;

        // preload first weight fragment (independent of gather below)
        float4 bv;
        {
            float4 b = __ldg((const float4*)(W + (size_t)lrow * D) + (lk4 >> 2));
            if (W2) {
                float4 w = __ldg((const float4*)(W2 + (size_t)lrow * D) + (lk4 >> 2));
                b.x += w.x; b.y += w.y; b.z += w.z; b.w += w.w;
            }
            bv = b;
        }

        // ---- fill S with this source's 128x128 tile (tf32-rounded) ----
        if (isAgg) {
            int r = aggR[s];
            const float* __restrict__ xs = aggX[s];
            for (int i = 0; i < 16; i++) {
                int node = m0 + i * 8 + wid;
                float4 a0 = make_float4(0.f, 0.f, 0.f, 0.f);
                float4 a1 = a0, a2 = a0, a3 = a0;
                float inv = 0.f;
                if (node < N_NODE) {
                    int beg = g_offs[r][node];
                    int end = g_offs[r][node + 1];
                    for (int e = beg; e < end; e += 32) {
                        int n = end - e;
                        if (n > 32) n = 32;
                        int idx = (lane < n) ? g_sorted[r][e + lane] : 0;
                        int j = 0;
                        for (; j + 4 <= n; j += 4) {
                            int s0 = __shfl_sync(0xffffffffu, idx, j + 0);
                            int s1 = __shfl_sync(0xffffffffu, idx, j + 1);
                            int s2 = __shfl_sync(0xffffffffu, idx, j + 2);
                            int s3 = __shfl_sync(0xffffffffu, idx, j + 3);
                            float4 v0 = __ldg((const float4*)(xs + (size_t)s0 * D) + lane);
                            float4 v1 = __ldg((const float4*)(xs + (size_t)s1 * D) + lane);
                            float4 v2 = __ldg((const float4*)(xs + (size_t)s2 * D) + lane);
                            float4 v3 = __ldg((const float4*)(xs + (size_t)s3 * D) + lane);
                            a0.x += v0.x; a0.y += v0.y; a0.z += v0.z; a0.w += v0.w;
                            a1.x += v1.x; a1.y += v1.y; a1.z += v1.z; a1.w += v1.w;
                            a2.x += v2.x; a2.y += v2.y; a2.z += v2.z; a2.w += v2.w;
                            a3.x += v3.x; a3.y += v3.y; a3.z += v3.z; a3.w += v3.w;
                        }
                        for (; j < n; j++) {
                            int s0 = __shfl_sync(0xffffffffu, idx, j);
                            float4 v0 = __ldg((const float4*)(xs + (size_t)s0 * D) + lane);
                            a0.x += v0.x; a0.y += v0.y; a0.z += v0.z; a0.w += v0.w;
                        }
                    }
                    int deg = end - beg;
                    inv = (deg > 0) ? (1.0f / (float)deg) : 0.0f;
                }
                float4 o;
                o.x = to_tf32((a0.x + a1.x + a2.x + a3.x) * inv);
                o.y = to_tf32((a0.y + a1.y + a2.y + a3.y) * inv);
                o.z = to_tf32((a0.z + a1.z + a2.z + a3.z) * inv);
                o.w = to_tf32((a0.w + a1.w + a2.w + a3.w) * inv);
                *(float4*)&S[(i * 8 + wid) * SROW_S + lane * 4] = o;
            }
        } else {
            // coalesced fill from node features
            for (int idx = tid; idx < BM * 32; idx += 256) {
                int row = idx >> 5;
                int q   = idx & 31;
                int gm  = m0 + row;
                float4 v = (gm < N_NODE)
                    ? __ldg((const float4*)(xsrc + (size_t)gm * D) + q)
                    : make_float4(0.f, 0.f, 0.f, 0.f);
                v.x = to_tf32(v.x); v.y = to_tf32(v.y);
                v.z = to_tf32(v.z); v.w = to_tf32(v.w);
                *(float4*)&S[row * SROW_S + q * 4] = v;
            }
        }
        __syncthreads();

        // ---- 16 k-tiles of MMA: A from S, B from W via Bs ----
        for (int t = 0; t < 16; t++) {
            float4 bt;
            bt.x = to_tf32(bv.x); bt.y = to_tf32(bv.y);
            bt.z = to_tf32(bv.z); bt.w = to_tf32(bv.w);
            *(float4*)&Bs[lrow * SROW + lk4] = bt;
            __syncthreads();

            float4 bv2 = make_float4(0.f, 0.f, 0.f, 0.f);
            if (t + 1 < 16) {
                int kk = (t + 1) * BK;
                float4 b = __ldg((const float4*)(W + (size_t)lrow * D) + ((kk + lk4) >> 2));
                if (W2) {
                    float4 w = __ldg((const float4*)(W2 + (size_t)lrow * D) + ((kk + lk4) >> 2));
                    b.x += w.x; b.y += w.y; b.z += w.z; b.w += w.w;
                }
                bv2 = b;
            }

            int kk = t * BK;
            uint32_t a_[2][4];
            const float* Ab = &S[(warp_m * 32) * SROW_S + kk];
#pragma unroll
            for (int mt = 0; mt < 2; mt++) {
                a_[mt][0] = __float_as_uint(Ab[(mt * 16 + g)     * SROW_S + tig]);
                a_[mt][1] = __float_as_uint(Ab[(mt * 16 + g + 8) * SROW_S + tig]);
                a_[mt][2] = __float_as_uint(Ab[(mt * 16 + g)     * SROW_S + tig + 4]);
                a_[mt][3] = __float_as_uint(Ab[(mt * 16 + g + 8) * SROW_S + tig + 4]);
            }
            uint32_t b_[8][2];
            const float* Bb = &Bs[(warp_n * 64) * SROW];
#pragma unroll
            for (int nt = 0; nt < 8; nt++) {
                b_[nt][0] = __float_as_uint(Bb[(nt * 8 + g) * SROW + tig]);
                b_[nt][1] = __float_as_uint(Bb[(nt * 8 + g) * SROW + tig + 4]);
            }

#pragma unroll
            for (int mt = 0; mt < 2; mt++)
#pragma unroll
                for (int nt = 0; nt < 8; nt++)
                    MMA_TF32(acc[mt][nt], a_[mt], b_[nt]);

            __syncthreads();
            bv = bv2;
        }
    }

    // ---- epilogue: bias + scale, float2 stores per fragment row ----
    float bias_lo[8], bias_hi[8];
#pragma unroll
    for (int nt = 0; nt < 8; nt++) {
        int c = warp_n * 64 + nt * 8 + 2 * tig;
        float b0v = bias0[c];
        float b1v = bias0[c + 1];
        if (bias1) { b0v += bias1[c]; b1v += bias1[c + 1]; }
        bias_lo[nt] = b0v;
        bias_hi[nt] = b1v;
    }
#pragma unroll
    for (int mt = 0; mt < 2; mt++) {
        int r0 = m0 + warp_m * 32 + mt * 16 + g;
        int r1 = r0 + 8;
#pragma unroll
        for (int nt = 0; nt < 8; nt++) {
            int c = warp_n * 64 + nt * 8 + 2 * tig;
            if (r0 < N_NODE) {
                float2 o;
                o.x = scale * (acc[mt][nt][0] + bias_lo[nt]);
                o.y = scale * (acc[mt][nt][1] + bias_hi[nt]);
                *(float2*)&outp[(size_t)r0 * D + c] = o;
            }
            if (r1 < N_NODE) {
                float2 o;
                o.x = scale * (acc[mt][nt][2] + bias_lo[nt]);
                o.y = scale * (acc[mt][nt][3] + bias_hi[nt]);
                *(float2*)&outp[(size_t)r1 * D + c] = o;
            }
        }
    }
}

// ---------------- launcher ----------------
extern "C" void kernel_launch(void* const* d_in, const int* in_sizes, int n_in,
                              void* d_out, int out_size) {
    const float* x_user   = (const float*)d_in[0];
    const float* x_item   = (const float*)d_in[1];
    const int*   ei_rates = (const int*)d_in[2];
    const int*   ei_rev   = (const int*)d_in[3];
    const int*   ei_fol   = (const int*)d_in[4];
    const float* Wl_rates = (const float*)d_in[5];
    const float* bl_rates = (const float*)d_in[6];
    const float* Wr_rates = (const float*)d_in[7];
    const float* Wl_rev   = (const float*)d_in[8];
    const float* bl_rev   = (const float*)d_in[9];
    const float* Wr_rev   = (const float*)d_in[10];
    const float* Wl_fol   = (const float*)d_in[11];
    const float* bl_fol   = (const float*)d_in[12];
    const float* Wr_fol   = (const float*)d_in[13];

    float* outp = (float*)d_out;

    static int smem_set = 0;
    if (!smem_set) {
        cudaFuncSetAttribute(fused_agg_gemm_kernel,
                             cudaFuncAttributeMaxDynamicSharedMemorySize,
                             S_BYTES);
        smem_set = 1;
    }

    int nq = NREL * (N_EDGE / 4);
    // degree count (g_deg is zero: statics at load, scan3 re-zeros per run)
    count_kernel<<<(nq + 255) / 256, 256>>>(ei_rates, ei_rev, ei_fol);
    // prefix sums -> CSR offsets (+ re-zero g_deg for next replay)
    dim3 sg(NCHUNK, NREL);
    scan1_kernel<<<sg, 1024>>>();
    scan3_kernel<<<sg, 1024>>>();
    // bucket src ids by dst
    bucket_kernel<<<(nq + 255) / 256, 256>>>(ei_rates, ei_rev, ei_fol);
    // fused aggregation + TF32 GEMM (one block per output tile)
    GemmArgs A_{x_user, x_item,
                Wl_rates, bl_rates, Wr_rates,
                Wl_rev, bl_rev, Wr_rev,
                Wl_fol, bl_fol, Wr_fol,
                outp};
    fused_agg_gemm_kernel<<<2 * NB, 256, S_BYTES>>>(A_);
}